// round 6
// baseline (speedup 1.0000x reference)
#include <cuda_runtime.h>
#include <cuda_fp16.h>
#include <math.h>

// Radon transform: img 512x512 f32, angles 180 (int degrees 0..179)
// out[x*180 + a] = sum_y bilinear(img, sy, sx), zero outside image.

#define NIMG 512
#define NA   180
#define PAD  128
#define PW   768
#define CEN  255.5f
#define FXS  20                    // fixed-point fraction bits
#define FXF  1048576.0f            // 2^20
#define NSPLIT 4                   // y-chunks per detector line

// fp16 quad tables: entry = {half2(v00,v01), half2(v10,v11)} of the 2x2
// bilinear stencil at (r,q) of the zero-padded image / its transpose.
__device__ uint2  g_quadH [PW * PW];
__device__ uint2  g_quadTH[PW * PW];
__device__ float2 g_trig  [NA];                   // (cos, sin) per angle
__device__ float  g_part  [NSPLIT * NIMG * NA];   // partial sums per y-chunk

// Stage A: pad-orientation quad table, row-major coalesced reads. + trig.
__global__ __launch_bounds__(256) void quad_build_kernel(
    const float* __restrict__ img, const int* __restrict__ angles)
{
    int i = blockIdx.x * 256 + threadIdx.x;

    if (i < NA) {
        // Match reference precision: deg2rad in f32, then hi-prec sincos.
        float tf = (float)angles[i] * 0.017453292519943295f;
        double sd, cd;
        sincos((double)tf, &sd, &cd);
        g_trig[i] = make_float2((float)cd, (float)sd);
    }

    if (i >= PW * PW) return;
    int r = i / PW;
    int q = i - r * PW;
    int ir = r - PAD;
    int iq = q - PAD;

    bool r0 = ((unsigned)ir      < NIMG);
    bool r1 = ((unsigned)(ir+1)  < NIMG);
    bool q0 = ((unsigned)iq      < NIMG);
    bool q1 = ((unsigned)(iq+1)  < NIMG);

    float v00 = (r0 & q0) ? __ldg(img + ir * NIMG + iq)           : 0.0f;
    float v01 = (r0 & q1) ? __ldg(img + ir * NIMG + iq + 1)       : 0.0f;
    float v10 = (r1 & q0) ? __ldg(img + (ir + 1) * NIMG + iq)     : 0.0f;
    float v11 = (r1 & q1) ? __ldg(img + (ir + 1) * NIMG + iq + 1) : 0.0f;

    __half2 h01 = __floats2half2_rn(v00, v01);
    __half2 h23 = __floats2half2_rn(v10, v11);
    uint2 u;
    u.x = *reinterpret_cast<unsigned*>(&h01);
    u.y = *reinterpret_cast<unsigned*>(&h23);
    g_quadH[i] = u;
}

// Stage B: transposed table = tiled transpose + in-quad 2x2 swizzle.
// quadT[r][q] = (v00,v10,v01,v11) of quad[q][r].
__global__ __launch_bounds__(256) void quad_transpose_kernel() {
    __shared__ uint2 tile[32][33];
    const int tx = threadIdx.x;          // 0..31
    const int ty = threadIdx.y;          // 0..7
    const int bx = blockIdx.x * 32;
    const int by = blockIdx.y * 32;

    #pragma unroll
    for (int j = 0; j < 32; j += 8)
        tile[ty + j][tx] = g_quadH[(by + ty + j) * PW + (bx + tx)];
    __syncthreads();
    #pragma unroll
    for (int j = 0; j < 32; j += 8) {
        uint2 A = tile[tx][ty + j];
        uint2 B;
        B.x = __byte_perm(A.x, A.y, 0x5410);   // (v00, v10)
        B.y = __byte_perm(A.x, A.y, 0x7632);   // (v01, v11)
        g_quadTH[(bx + ty + j) * PW + (by + tx)] = B;
    }
}

// Main radon kernel.
// Block: 128 threads = 4 warps. Warp = 8 detectors x 4 y-phases.
// Grid: (512/32, 180, NSPLIT); each block does a 128-row y-chunk.
__global__ __launch_bounds__(128) void radon_kernel()
{
    const int lane   = threadIdx.x & 31;
    const int warpId = threadIdx.x >> 5;
    const int d      = lane & 7;
    const int yq     = lane >> 3;
    const int x      = blockIdx.x * 32 + warpId * 8 + d;
    const int a      = blockIdx.y;
    const int chunk  = blockIdx.z;

    const float2 cs = g_trig[a];
    const float co = cs.x;
    const float si = cs.y;

    const float xcn = (float)x - CEN;

    // Padded coords at y = chunk*128 + yq.
    float yc0 = (float)(chunk * 128 + yq) - CEN;
    float R0 = fmaf(-si, xcn, fmaf(co, yc0, CEN + (float)PAD));
    float Q0 = fmaf( co, xcn, fmaf(si, yc0, CEN + (float)PAD));
    float dR = co;
    float dQ = si;
    const uint2* base = g_quadH;

    // Transpose-swap: contiguous axis gets the larger per-lane step.
    if (fabsf(si) > fabsf(co)) {
        float t0 = R0; R0 = Q0; Q0 = t0;
        float t1 = dR; dR = dQ; dQ = t1;
        base = g_quadTH;
    }

    // Fixed-point s11.20 stepping; per-thread y-stride is 4.
    int Rfx = __float2int_rn(R0 * FXF);
    int Qfx = __float2int_rn(Q0 * FXF);
    int dR4 = __float2int_rn(dR * (4.0f * FXF));
    int dQ4 = __float2int_rn(dQ * (4.0f * FXF));

    float acc0 = 0.0f, acc1 = 0.0f;

    // 32 samples per thread: 8 batches of 4.
    #pragma unroll 2
    for (int it = 0; it < 8; ++it) {
        int   idxv[4];
        float wrv[4], wqv[4];
        #pragma unroll
        for (int j = 0; j < 4; ++j) {
            int ri = Rfx >> FXS;
            int qi = Qfx >> FXS;
            idxv[j] = ri * PW + qi;
            int wrb = 0x3F800000 | ((Rfx & 0xFFFFF) << 3);
            int wqb = 0x3F800000 | ((Qfx & 0xFFFFF) << 3);
            wrv[j] = __int_as_float(wrb) - 1.0f;
            wqv[j] = __int_as_float(wqb) - 1.0f;
            Rfx += dR4;
            Qfx += dQ4;
        }
        uint2 u0 = __ldg(base + idxv[0]);
        uint2 u1 = __ldg(base + idxv[1]);
        uint2 u2 = __ldg(base + idxv[2]);
        uint2 u3 = __ldg(base + idxv[3]);

        {
            float2 t = __half22float2(*reinterpret_cast<__half2*>(&u0.x));
            float2 b = __half22float2(*reinterpret_cast<__half2*>(&u0.y));
            float top = fmaf(wqv[0], t.y - t.x, t.x);
            float bot = fmaf(wqv[0], b.y - b.x, b.x);
            acc0 += fmaf(wrv[0], bot - top, top);
        }
        {
            float2 t = __half22float2(*reinterpret_cast<__half2*>(&u1.x));
            float2 b = __half22float2(*reinterpret_cast<__half2*>(&u1.y));
            float top = fmaf(wqv[1], t.y - t.x, t.x);
            float bot = fmaf(wqv[1], b.y - b.x, b.x);
            acc1 += fmaf(wrv[1], bot - top, top);
        }
        {
            float2 t = __half22float2(*reinterpret_cast<__half2*>(&u2.x));
            float2 b = __half22float2(*reinterpret_cast<__half2*>(&u2.y));
            float top = fmaf(wqv[2], t.y - t.x, t.x);
            float bot = fmaf(wqv[2], b.y - b.x, b.x);
            acc0 += fmaf(wrv[2], bot - top, top);
        }
        {
            float2 t = __half22float2(*reinterpret_cast<__half2*>(&u3.x));
            float2 b = __half22float2(*reinterpret_cast<__half2*>(&u3.y));
            float top = fmaf(wqv[3], t.y - t.x, t.x);
            float bot = fmaf(wqv[3], b.y - b.x, b.x);
            acc1 += fmaf(wrv[3], bot - top, top);
        }
    }

    float acc = acc0 + acc1;
    // Reduce over the 4 y-phases (lanes d, d+8, d+16, d+24).
    acc += __shfl_xor_sync(0xffffffffu, acc, 16);
    acc += __shfl_xor_sync(0xffffffffu, acc, 8);

    if (lane < 8)
        g_part[(chunk * NIMG + x) * NA + a] = acc;
}

// Combine the NSPLIT partial sums (deterministic fixed order).
__global__ __launch_bounds__(256) void reduce_kernel(float* __restrict__ out)
{
    int i = blockIdx.x * 256 + threadIdx.x;
    if (i >= NIMG * NA) return;
    float s = g_part[i];
    #pragma unroll
    for (int c = 1; c < NSPLIT; ++c)
        s += g_part[c * NIMG * NA + i];
    out[i] = s;
}

extern "C" void kernel_launch(void* const* d_in, const int* in_sizes, int n_in,
                              void* d_out, int out_size) {
    const float* img    = (const float*)d_in[0];
    const int*   angles = (const int*)d_in[1];
    float*       out    = (float*)d_out;

    quad_build_kernel<<<(PW * PW + 255) / 256, 256>>>(img, angles);

    dim3 tb(32, 8);
    dim3 tg(PW / 32, PW / 32);
    quad_transpose_kernel<<<tg, tb>>>();

    dim3 rg(NIMG / 32, NA, NSPLIT);
    radon_kernel<<<rg, 128>>>();

    reduce_kernel<<<(NIMG * NA + 255) / 256, 256>>>(out);
}

// round 7
// speedup vs baseline: 1.2240x; 1.2240x over previous
#include <cuda_runtime.h>
#include <math.h>

// Radon transform: img 512x512 f32, angles 180 (int degrees 0..179)
// out[x*180 + a] = sum_y bilinear(img, sy, sx), zero outside image.

#define NIMG 512
#define NA   180
#define PAD  128
#define PW   768
#define CEN  255.5f
#define FXS  20                    // fixed-point fraction bits
#define FXF  1048576.0f            // 2^20
#define NSPLIT 4                   // y-chunks per detector line

// u16 quad tables: entry = {u00|u01<<16, u10|u11<<16}, u = round(v*65536),
// v = pixel of the zero-padded image (2x2 stencil at (r,q)) / its transpose.
__device__ uint2  g_quadU [PW * PW];
__device__ uint2  g_quadTU[PW * PW];
__device__ float2 g_trig  [NA];                   // (cos, sin) per angle
__device__ float  g_part  [NIMG * NA * NSPLIT];   // partials, [(x,a)][chunk]

__device__ __forceinline__ unsigned q16(float v) {
    unsigned u = __float2uint_rn(v * 65536.0f);
    return u > 65535u ? 65535u : u;
}

// Stage A: pad-orientation quad table, coalesced reads. + trig table.
__global__ __launch_bounds__(256) void quad_build_kernel(
    const float* __restrict__ img, const int* __restrict__ angles)
{
    int i = blockIdx.x * 256 + threadIdx.x;

    if (i < NA) {
        // Match reference precision: deg2rad in f32, then hi-prec sincos.
        float tf = (float)angles[i] * 0.017453292519943295f;
        double sd, cd;
        sincos((double)tf, &sd, &cd);
        g_trig[i] = make_float2((float)cd, (float)sd);
    }

    if (i >= PW * PW) return;
    int r = i / PW;
    int q = i - r * PW;
    int ir = r - PAD;
    int iq = q - PAD;

    bool r0 = ((unsigned)ir     < NIMG);
    bool r1 = ((unsigned)(ir+1) < NIMG);
    bool q0 = ((unsigned)iq     < NIMG);
    bool q1 = ((unsigned)(iq+1) < NIMG);

    float v00 = (r0 & q0) ? __ldg(img + ir * NIMG + iq)           : 0.0f;
    float v01 = (r0 & q1) ? __ldg(img + ir * NIMG + iq + 1)       : 0.0f;
    float v10 = (r1 & q0) ? __ldg(img + (ir + 1) * NIMG + iq)     : 0.0f;
    float v11 = (r1 & q1) ? __ldg(img + (ir + 1) * NIMG + iq + 1) : 0.0f;

    uint2 u;
    u.x = q16(v00) | (q16(v01) << 16);
    u.y = q16(v10) | (q16(v11) << 16);
    g_quadU[i] = u;
}

// Stage B: transposed table = tiled transpose + in-quad component swizzle.
// quadT[r][q] = (v00, v10, v01, v11) of quad[q][r].
__global__ __launch_bounds__(256) void quad_transpose_kernel() {
    __shared__ uint2 tile[32][33];
    const int tx = threadIdx.x;          // 0..31
    const int ty = threadIdx.y;          // 0..7
    const int bx = blockIdx.x * 32;
    const int by = blockIdx.y * 32;

    #pragma unroll
    for (int j = 0; j < 32; j += 8)
        tile[ty + j][tx] = g_quadU[(by + ty + j) * PW + (bx + tx)];
    __syncthreads();
    #pragma unroll
    for (int j = 0; j < 32; j += 8) {
        uint2 A = tile[tx][ty + j];
        uint2 B;
        B.x = __byte_perm(A.x, A.y, 0x5410);   // (u00, u10)
        B.y = __byte_perm(A.x, A.y, 0x7632);   // (u01, u11)
        g_quadTU[(bx + ty + j) * PW + (by + tx)] = B;
    }
}

// Decode u16 -> 1.0f + v (exact mantissa splice).
__device__ __forceinline__ float spl_lo(unsigned u) {
    return __uint_as_float(0x3F800000u | ((u << 7) & 0x007FFF80u));
}
__device__ __forceinline__ float spl_hi(unsigned u) {
    return __uint_as_float(0x3F800000u | ((u >> 9) & 0x007FFF80u));
}

// Main radon kernel.
// Block: 128 threads = 4 warps. Warp = 8 detectors x 4 y-phases.
// Grid: (512/32, 180, NSPLIT); each block does a 128-row y-chunk.
__global__ __launch_bounds__(128) void radon_kernel()
{
    const int lane   = threadIdx.x & 31;
    const int warpId = threadIdx.x >> 5;
    const int d      = lane & 7;
    const int yq     = lane >> 3;
    const int x      = blockIdx.x * 32 + warpId * 8 + d;
    const int a      = blockIdx.y;
    const int chunk  = blockIdx.z;

    const float2 cs = g_trig[a];
    const float co = cs.x;
    const float si = cs.y;

    const float xcn = (float)x - CEN;

    // Padded coords at y = chunk*128 + yq.
    float yc0 = (float)(chunk * 128 + yq) - CEN;
    float R0 = fmaf(-si, xcn, fmaf(co, yc0, CEN + (float)PAD));
    float Q0 = fmaf( co, xcn, fmaf(si, yc0, CEN + (float)PAD));
    float dR = co;
    float dQ = si;
    const uint2* base = g_quadU;

    // Transpose-swap: contiguous axis gets the larger per-lane step.
    if (fabsf(si) > fabsf(co)) {
        float t0 = R0; R0 = Q0; Q0 = t0;
        float t1 = dR; dR = dQ; dQ = t1;
        base = g_quadTU;
    }

    // Fixed-point s11.20 stepping; per-thread y-stride is 4.
    int Rfx = __float2int_rn(R0 * FXF);
    int Qfx = __float2int_rn(Q0 * FXF);
    int dR4 = __float2int_rn(dR * (4.0f * FXF));
    int dQ4 = __float2int_rn(dQ * (4.0f * FXF));

    float acc0 = 0.0f, acc1 = 0.0f;

    // 32 samples per thread: 8 batches of 4.
    #pragma unroll 2
    for (int it = 0; it < 8; ++it) {
        int   idxv[4];
        float wrv[4], wqv[4];
        #pragma unroll
        for (int j = 0; j < 4; ++j) {
            int ri = Rfx >> FXS;
            int qi = Qfx >> FXS;
            idxv[j] = ri * PW + qi;
            int wrb = 0x3F800000 | ((Rfx & 0xFFFFF) << 3);
            int wqb = 0x3F800000 | ((Qfx & 0xFFFFF) << 3);
            wrv[j] = __int_as_float(wrb) - 1.0f;
            wqv[j] = __int_as_float(wqb) - 1.0f;
            Rfx += dR4;
            Qfx += dQ4;
        }
        uint2 u0 = __ldg(base + idxv[0]);
        uint2 u1 = __ldg(base + idxv[1]);
        uint2 u2 = __ldg(base + idxv[2]);
        uint2 u3 = __ldg(base + idxv[3]);

        // bil(1+v) = 1 + bil(v): bias handled once after the loop.
        {
            float t0 = spl_lo(u0.x), t1 = spl_hi(u0.x);
            float b0 = spl_lo(u0.y), b1 = spl_hi(u0.y);
            float top = fmaf(wqv[0], t1 - t0, t0);
            float bot = fmaf(wqv[0], b1 - b0, b0);
            acc0 += fmaf(wrv[0], bot - top, top);
        }
        {
            float t0 = spl_lo(u1.x), t1 = spl_hi(u1.x);
            float b0 = spl_lo(u1.y), b1 = spl_hi(u1.y);
            float top = fmaf(wqv[1], t1 - t0, t0);
            float bot = fmaf(wqv[1], b1 - b0, b0);
            acc1 += fmaf(wrv[1], bot - top, top);
        }
        {
            float t0 = spl_lo(u2.x), t1 = spl_hi(u2.x);
            float b0 = spl_lo(u2.y), b1 = spl_hi(u2.y);
            float top = fmaf(wqv[2], t1 - t0, t0);
            float bot = fmaf(wqv[2], b1 - b0, b0);
            acc0 += fmaf(wrv[2], bot - top, top);
        }
        {
            float t0 = spl_lo(u3.x), t1 = spl_hi(u3.x);
            float b0 = spl_lo(u3.y), b1 = spl_hi(u3.y);
            float top = fmaf(wqv[3], t1 - t0, t0);
            float bot = fmaf(wqv[3], b1 - b0, b0);
            acc1 += fmaf(wrv[3], bot - top, top);
        }
    }

    // Remove the +1 bias from 32 samples, then reduce over 4 y-phases.
    float acc = (acc0 + acc1) - 32.0f;
    acc += __shfl_xor_sync(0xffffffffu, acc, 16);
    acc += __shfl_xor_sync(0xffffffffu, acc, 8);

    if (lane < 8)
        g_part[(x * NA + a) * NSPLIT + chunk] = acc;
}

// Combine the NSPLIT partial sums (one float4 per output, fixed order).
__global__ __launch_bounds__(256) void reduce_kernel(float* __restrict__ out)
{
    int i = blockIdx.x * 256 + threadIdx.x;
    if (i >= NIMG * NA) return;
    float4 p = *reinterpret_cast<const float4*>(g_part + i * NSPLIT);
    out[i] = (p.x + p.y) + (p.z + p.w);
}

extern "C" void kernel_launch(void* const* d_in, const int* in_sizes, int n_in,
                              void* d_out, int out_size) {
    const float* img    = (const float*)d_in[0];
    const int*   angles = (const int*)d_in[1];
    float*       out    = (float*)d_out;

    quad_build_kernel<<<(PW * PW + 255) / 256, 256>>>(img, angles);

    dim3 tb(32, 8);
    dim3 tg(PW / 32, PW / 32);
    quad_transpose_kernel<<<tg, tb>>>();

    dim3 rg(NIMG / 32, NA, NSPLIT);
    radon_kernel<<<rg, 128>>>();

    reduce_kernel<<<(NIMG * NA + 255) / 256, 256>>>(out);
}

// round 8
// speedup vs baseline: 1.2865x; 1.0511x over previous
#include <cuda_runtime.h>
#include <math.h>

// Radon transform: img 512x512 f32, angles 180 (int degrees 0..179)
// out[x*180 + a] = sum_y bilinear(img, sy, sx), zero outside image.

#define NIMG 512
#define NA   180
#define PAD  128
#define PW   768
#define CEN  255.5f
#define FXS  20                    // fixed-point fraction bits
#define FXF  1048576.0f            // 2^20

// Quad tables: entry(r,q) = (v[r][q], v[r][q+1], v[r+1][q], v[r+1][q+1])
// of the zero-padded image / its transpose.
__device__ float4 g_quad [PW * PW];
__device__ float4 g_quadT[PW * PW];
__device__ float2 g_trig [NA];     // (cos, sin) per angle

// Fused builder: one smem img tile serves both orientations (all writes
// coalesced). Grid 24x24, block 32x8. Block (bx,by) writes
//   g_quad rows [by*32..), cols [bx*32..)   and
//   g_quadT rows [bx*32..), cols [by*32..)  (the mirrored tile).
__global__ __launch_bounds__(256) void quad_build_kernel(
    const float* __restrict__ img, const int* __restrict__ angles)
{
    __shared__ float tile[33][36];
    const int tx = threadIdx.x;             // 0..31
    const int ty = threadIdx.y;             // 0..7
    const int lin = ty * 32 + tx;           // 0..255
    const int bx = blockIdx.x * 32;
    const int by = blockIdx.y * 32;

    if (blockIdx.x == 0 && blockIdx.y == 0 && lin < NA) {
        // Match reference precision: deg2rad in f32, then hi-prec sincos.
        float tf = (float)angles[lin] * 0.017453292519943295f;
        double sd, cd;
        sincos((double)tf, &sd, &cd);
        g_trig[lin] = make_float2((float)cd, (float)sd);
    }

    // Load 33x33 img tile at (by-PAD, bx-PAD), zero outside.
    for (int t = lin; t < 33 * 33; t += 256) {
        int i = t / 33;
        int j = t - i * 33;
        int ir = by - PAD + i;
        int iq = bx - PAD + j;
        float v = 0.0f;
        if ((unsigned)ir < NIMG && (unsigned)iq < NIMG)
            v = __ldg(img + ir * NIMG + iq);
        tile[i][j] = v;
    }
    __syncthreads();

    // Each thread emits 4 rows of each table.
    #pragma unroll
    for (int j = 0; j < 32; j += 8) {
        int i = ty + j;
        // Straight orientation: quad[by+i][bx+tx]
        float v00 = tile[i][tx];
        float v01 = tile[i][tx + 1];
        float v10 = tile[i + 1][tx];
        float v11 = tile[i + 1][tx + 1];
        g_quad[(by + i) * PW + (bx + tx)] = make_float4(v00, v01, v10, v11);
        // Transposed orientation: quadT[bx+i][by+tx], imgT[r][q]=img[q][r]:
        // w00 = tile[tx][i], w01 = tile[tx+1][i], w10 = tile[tx][i+1], ...
        float w00 = tile[tx][i];
        float w01 = tile[tx + 1][i];
        float w10 = tile[tx][i + 1];
        float w11 = tile[tx + 1][i + 1];
        g_quadT[(bx + i) * PW + (by + tx)] = make_float4(w00, w01, w10, w11);
    }
}

// Main radon kernel.
// Block: 512 threads = 16 warps = 4 det-groups x 4 y-chunks.
// Warp: 8 detectors x 4 y-phases. Grid: (512/32, 180).
__global__ __launch_bounds__(512, 3) void radon_kernel(float* __restrict__ out)
{
    __shared__ float s_red[4][32];

    const int lane  = threadIdx.x & 31;
    const int w     = threadIdx.x >> 5;     // 0..15
    const int g     = w & 3;                // detector group
    const int c     = w >> 2;               // y chunk
    const int d     = lane & 7;
    const int yq    = lane >> 3;
    const int x     = blockIdx.x * 32 + g * 8 + d;
    const int a     = blockIdx.y;

    const float2 cs = g_trig[a];
    const float co = cs.x;
    const float si = cs.y;

    const float xcn = (float)x - CEN;

    // Padded coords at y0 = c*128 + yq; samples at y0 + 4k, k = 0..31.
    float yc0 = (float)(c * 128 + yq) - CEN;
    float R0 = fmaf(-si, xcn, fmaf(co, yc0, CEN + (float)PAD));
    float Q0 = fmaf( co, xcn, fmaf(si, yc0, CEN + (float)PAD));
    float dR = co;
    float dQ = si;
    const float4* base = g_quad;

    // Transpose-swap: contiguous axis gets the larger per-lane step.
    if (fabsf(si) > fabsf(co)) {
        float t0 = R0; R0 = Q0; Q0 = t0;
        float t1 = dR; dR = dQ; dQ = t1;
        base = g_quadT;
    }

    const float dR4f = dR * 4.0f;
    const float dQ4f = dQ * 4.0f;

    // Clip to the k-range whose quads can be nonzero (skip is bit-exact:
    // outside this range every fetched quad is exactly 0).
    // Nonzero region: coord in [PAD-1, PAD+512) -> widened [126.9, 640.1].
    float invR = 1.0f / dR4f;
    float invQ = 1.0f / dQ4f;
    float aR = (126.9f - R0) * invR, bR = (640.1f - R0) * invR;
    float aQ = (126.9f - Q0) * invQ, bQ = (640.1f - Q0) * invQ;
    float kminf = fmaxf(fminf(aR, bR), fminf(aQ, bQ));
    float kmaxf = fminf(fmaxf(aR, bR), fmaxf(aQ, bQ));
    int klo = max(0,  (int)floorf(kminf));
    int khi = min(31, (int)ceilf (kmaxf));

    // Fixed-point s11.20 stepping (y-stride 4 per k).
    int dR4 = __float2int_rn(dR * (4.0f * FXF));
    int dQ4 = __float2int_rn(dQ * (4.0f * FXF));
    int k   = klo & ~3;
    int Rfx = __float2int_rn(R0 * FXF) + k * dR4;
    int Qfx = __float2int_rn(Q0 * FXF) + k * dQ4;

    float acc0 = 0.0f, acc1 = 0.0f;

    #pragma unroll 2
    for (; k <= khi; k += 4) {
        int   idxv[4];
        float wrv[4], wqv[4];
        #pragma unroll
        for (int j = 0; j < 4; ++j) {
            int ri = Rfx >> FXS;
            int qi = Qfx >> FXS;
            idxv[j] = ri * PW + qi;
            // exact fraction via mantissa splice
            int wrb = 0x3F800000 | ((Rfx & 0xFFFFF) << 3);
            int wqb = 0x3F800000 | ((Qfx & 0xFFFFF) << 3);
            wrv[j] = __int_as_float(wrb) - 1.0f;
            wqv[j] = __int_as_float(wqb) - 1.0f;
            Rfx += dR4;
            Qfx += dQ4;
        }
        float4 v0 = __ldg(base + idxv[0]);
        float4 v1 = __ldg(base + idxv[1]);
        float4 v2 = __ldg(base + idxv[2]);
        float4 v3 = __ldg(base + idxv[3]);

        {
            float top = fmaf(wqv[0], v0.y - v0.x, v0.x);
            float bot = fmaf(wqv[0], v0.w - v0.z, v0.z);
            acc0 += fmaf(wrv[0], bot - top, top);
        }
        {
            float top = fmaf(wqv[1], v1.y - v1.x, v1.x);
            float bot = fmaf(wqv[1], v1.w - v1.z, v1.z);
            acc1 += fmaf(wrv[1], bot - top, top);
        }
        {
            float top = fmaf(wqv[2], v2.y - v2.x, v2.x);
            float bot = fmaf(wqv[2], v2.w - v2.z, v2.z);
            acc0 += fmaf(wrv[2], bot - top, top);
        }
        {
            float top = fmaf(wqv[3], v3.y - v3.x, v3.x);
            float bot = fmaf(wqv[3], v3.w - v3.z, v3.z);
            acc1 += fmaf(wrv[3], bot - top, top);
        }
    }

    float acc = acc0 + acc1;
    // Reduce over the 4 y-phases within the warp.
    acc += __shfl_xor_sync(0xffffffffu, acc, 16);
    acc += __shfl_xor_sync(0xffffffffu, acc, 8);

    if (lane < 8)
        s_red[c][g * 8 + d] = acc;
    __syncthreads();

    // Warp 0 combines the 4 y-chunks and writes 32 detectors.
    if (w == 0) {
        float s = (s_red[0][lane] + s_red[1][lane])
                + (s_red[2][lane] + s_red[3][lane]);
        out[(blockIdx.x * 32 + lane) * NA + a] = s;
    }
}

extern "C" void kernel_launch(void* const* d_in, const int* in_sizes, int n_in,
                              void* d_out, int out_size) {
    const float* img    = (const float*)d_in[0];
    const int*   angles = (const int*)d_in[1];
    float*       out    = (float*)d_out;

    dim3 tb(32, 8);
    dim3 tg(PW / 32, PW / 32);
    quad_build_kernel<<<tg, tb>>>(img, angles);

    dim3 rg(NIMG / 32, NA);
    radon_kernel<<<rg, 512>>>(out);
}